// round 15
// baseline (speedup 1.0000x reference)
#include <cuda_runtime.h>

#define Bb 16
#define Tt 160
#define Uu 80
#define U1 81
#define Vv 512
#define NDIAG 240     // diagonals d = t+u in [0,239]
#define DSTR 88       // diagonal row stride (floats), 16B aligned
#define L2E 1.4426950408889634f
#define LN2 0.6931471805599453f
#define PADB Bb       // pad-fill blocks prepended to lse grid
#define RNORM 12      // diagonals between renormalizations
#define SC 9          // tables pre-scaled by 2^SC (2^9 = 512)

// Scratch (allocation-free rule). Tables: LINEAR probabilities * 2^SC,
// anti-diagonal layout. Dead rows / geometry pads hold exact 0.0f.
__device__ float g_blank[Bb*NDIAG*DSTR];
__device__ float g_lab  [Bb*NDIAG*DSTR];
__device__ float g_ll   [Bb];
__device__ int   g_done;              // dp completion counter; self-resetting

// ---------------------------------------------------------------------------
__device__ __forceinline__ float exp_fast(float x) {   // scalar FMA-only e^x
    const float MAGIC = 12582912.0f;                    // 1.5 * 2^23
    float z = fmaf(x, L2E, MAGIC);
    float w = z - MAGIC;
    float f = fmaf(x, L2E, -w);
    float p =               9.6181291076e-3f;
    p = fmaf(p, f, 5.5504108664e-2f);
    p = fmaf(p, f, 2.4022650696e-1f);
    p = fmaf(p, f, 6.9314718056e-1f);
    p = fmaf(p, f, 1.0f);
    return __int_as_float(__float_as_int(p) + (__float_as_int(z) << 23));
}

// ---- packed f32x2 exp: e^x0 + e^x1 in ~half the FMA-pipe instructions ----
__device__ __forceinline__ unsigned long long pk2(float lo, float hi) {
    unsigned long long r;
    asm("mov.b64 %0, {%1, %2};" : "=l"(r) : "f"(lo), "f"(hi));
    return r;
}
struct ExpC {
    unsigned long long l2e, mag, nmag, neg1, c4, c3, c2, c1, c0;
};
__device__ __forceinline__ ExpC make_expc() {
    ExpC C;
    C.l2e  = pk2(L2E, L2E);
    C.mag  = pk2(12582912.0f, 12582912.0f);
    C.nmag = pk2(-12582912.0f, -12582912.0f);
    C.neg1 = pk2(-1.0f, -1.0f);
    C.c4   = pk2(9.6181291076e-3f, 9.6181291076e-3f);
    C.c3   = pk2(5.5504108664e-2f, 5.5504108664e-2f);
    C.c2   = pk2(2.4022650696e-1f, 2.4022650696e-1f);
    C.c1   = pk2(6.9314718056e-1f, 6.9314718056e-1f);
    C.c0   = pk2(1.0f, 1.0f);
    return C;
}
__device__ __forceinline__ float exp2sum(float x0, float x1, const ExpC& C) {
    unsigned long long X = pk2(x0, x1), t, z, w, f, p;
    asm("mul.rn.f32x2 %0, %1, %2;"     : "=l"(t) : "l"(X), "l"(C.l2e));
    asm("add.rn.f32x2 %0, %1, %2;"     : "=l"(z) : "l"(t), "l"(C.mag));
    asm("add.rn.f32x2 %0, %1, %2;"     : "=l"(w) : "l"(z), "l"(C.nmag));
    asm("fma.rn.f32x2 %0, %1, %2, %3;" : "=l"(f) : "l"(w), "l"(C.neg1), "l"(t));
    asm("fma.rn.f32x2 %0, %1, %2, %3;" : "=l"(p) : "l"(C.c4), "l"(f), "l"(C.c3));
    asm("fma.rn.f32x2 %0, %1, %2, %3;" : "=l"(p) : "l"(p), "l"(f), "l"(C.c2));
    asm("fma.rn.f32x2 %0, %1, %2, %3;" : "=l"(p) : "l"(p), "l"(f), "l"(C.c1));
    asm("fma.rn.f32x2 %0, %1, %2, %3;" : "=l"(p) : "l"(p), "l"(f), "l"(C.c0));
    unsigned int z0, z1, p0, p1;
    asm("mov.b64 {%0, %1}, %2;" : "=r"(z0), "=r"(z1) : "l"(z));
    asm("mov.b64 {%0, %1}, %2;" : "=r"(p0), "=r"(p1) : "l"(p));
    float r0 = __int_as_float((int)(p0 + (z0 << 23)));
    float r1 = __int_as_float((int)(p1 + (z1 << 23)));
    return r0 + r1;
}

__device__ __forceinline__ void cp16(unsigned int s, const void* g) {
    asm volatile("cp.async.cg.shared.global [%0], [%1], 16;" :: "r"(s), "l"(g));
}

__device__ __forceinline__ float warp_max(float x) {
#pragma unroll
    for (int o = 16; o; o >>= 1) x = fmaxf(x, __shfl_xor_sync(0xffffffffu, x, o));
    return x;
}
__device__ __forceinline__ float warp_sum(float x) {
#pragma unroll
    for (int o = 16; o; o >>= 1) x += __shfl_xor_sync(0xffffffffu, x, o);
    return x;
}

// ---------------------------------------------------------------------------
// Kernel 1: blocks [0,PADB): pad fill (0.0f). Blocks >= PADB: per-row softmax
// denominator via packed f32x2 exp; emits LINEAR probs * 2^SC.
// ---------------------------------------------------------------------------
__global__ void __launch_bounds__(256) lse_kernel(const float* __restrict__ logits,
                                                  const int* __restrict__ targets,
                                                  const int* __restrict__ tl_arr,
                                                  const int* __restrict__ ul_arr) {
    cudaTriggerProgrammaticLaunchCompletion();

    if (blockIdx.x < PADB) {
        int b = blockIdx.x;
        float* bbl = g_blank + b * NDIAG * DSTR;
        float* bla = g_lab   + b * NDIAG * DSTR;
        for (int idx = threadIdx.x; idx < NDIAG * DSTR; idx += 256) {
            int d = idx / DSTR;
            int u = idx - d * DSTR;
            int lo = max(0, d - 159), hi = min(d, 80);
            if (u < lo || u > hi) { bbl[idx] = 0.0f; bla[idx] = 0.0f; }
        }
        return;
    }

    int gw   = ((blockIdx.x - PADB) * 256 + threadIdx.x) >> 5;  // row id
    int lane = threadIdx.x & 31;

    int u  = gw % U1;
    int bt = gw / U1;
    int t  = bt % Tt;
    int b  = bt / Tt;
    int o  = (b * NDIAG + (t + u)) * DSTR + u;
    if (t >= __ldg(tl_arr + b) || u > __ldg(ul_arr + b)) {  // dead row -> 0
        if (lane == 0) { g_blank[o] = 0.0f; g_lab[o] = 0.0f; }
        return;
    }

    const float4* p = reinterpret_cast<const float4*>(logits) + (size_t)gw * (Vv / 4);
    float4 a  = __ldcs(p + lane);
    float4 b4 = __ldcs(p + lane + 32);
    float4 c  = __ldcs(p + lane + 64);
    float4 dd = __ldcs(p + lane + 96);

    ExpC C = make_expc();
    float s0 = exp2sum(a.x,  a.y,  C) + exp2sum(a.z,  a.w,  C);
    float s1 = exp2sum(b4.x, b4.y, C) + exp2sum(b4.z, b4.w, C);
    float s2 = exp2sum(c.x,  c.y,  C) + exp2sum(c.z,  c.w,  C);
    float s3 = exp2sum(dd.x, dd.y, C) + exp2sum(dd.z, dd.w, C);
    float s  = (s0 + s1) + (s2 + s3);
#pragma unroll
    for (int o2 = 16; o2; o2 >>= 1) s += __shfl_xor_sync(0xffffffffu, s, o2);

    float blank_logit = __shfl_sync(0xffffffffu, dd.w, 31);  // element 511

    if (lane == 0) {
        float rs = __fdividef(512.0f, s);     // 2^SC / sum  (MUFU rcp path)
        int tgt = targets[b * Uu + min(u, Uu - 1)];
        float lab_logit = __ldg(logits + (size_t)gw * Vv + tgt);
        g_blank[o] = exp_fast(blank_logit) * rs;   // pb * 2^SC
        g_lab[o]   = exp_fast(lab_logit)   * rs;   // pl * 2^SC
    }
}

// ---------------------------------------------------------------------------
// Kernel 2: MITM DP in LINEAR domain, one 128-thread block per batch (PDL).
//   warp0: forward alpha to cut dm (1 MUL + 1 FMA per cell per diagonal)
//   warp1: backward beta to dm; warps 2-3 assist cp.async preload then exit.
// Renorm every RNORM diagonals: warp-max -> scale by 2^(127-e), accumulate k.
// Combine: ll = lg2(sum_u A'[u]B'[u]) - SC*(dtar+1) + KF + KB   (log2 domain).
// ---------------------------------------------------------------------------
__global__ void __launch_bounds__(128) dp_kernel(const int* __restrict__ tl_arr,
                                                 const int* __restrict__ ul_arr,
                                                 float* __restrict__ out) {
    extern __shared__ float sm[];
    float* s_bl  = sm;
    float* s_la  = sm + NDIAG * DSTR;
    float* s_alp = sm + 2 * NDIAG * DSTR;        // 88: alpha' at the cut
    float* s_bet = s_alp + 88;                   // 88: beta'  at the cut
    int*   s_ki  = reinterpret_cast<int*>(s_bet + 88);  // [KF, KB]
    int b = blockIdx.x;

    int tl = __ldg(tl_arr + b), ul = __ldg(ul_arr + b);
    int dtar = tl - 1 + ul;
    int dm   = dtar >> 1;
    int n4   = (dtar + 1) * (DSTR / 4);
    const float4* gb = reinterpret_cast<const float4*>(g_blank + b * NDIAG * DSTR);
    const float4* gl = reinterpret_cast<const float4*>(g_lab   + b * NDIAG * DSTR);
    unsigned int sb = (unsigned int)__cvta_generic_to_shared(s_bl);
    unsigned int sl = (unsigned int)__cvta_generic_to_shared(s_la);

    cudaGridDependencySynchronize();             // HW wait on lse grid

    for (int i = threadIdx.x; i < n4; i += 128) {
        cp16(sb + 16u * i, gb + i);
        cp16(sl + 16u * i, gl + i);
    }
    asm volatile("cp.async.commit_group;");
    asm volatile("cp.async.wait_group 0;");
    __syncthreads();

    int wid  = threadIdx.x >> 5;
    if (wid >= 2) return;                        // preload-only warps exit
    int lane = threadIdx.x & 31;
    int u0   = lane * 4;
    int uoff = min(u0, 84);
    bool m0 = (u0     <= ul), m1 = (u0 + 1 <= ul),
         m2 = (u0 + 2 <= ul), m3 = (u0 + 3 <= ul);

    if (wid == 0) {
        // =================== FORWARD alpha': diag 1 .. dm ====================
        float v0 = (lane == 0) ? 1.0f : 0.0f, v1 = 0.0f, v2 = 0.0f, v3 = 0.0f;
        int K = 0, cd = RNORM;
        float4 cbl = *reinterpret_cast<const float4*>(s_bl + uoff);  // row 0
        float4 cla = *reinterpret_cast<const float4*>(s_la + uoff);
        for (int d = 1; d <= dm; ++d) {
            float4 nbl = *reinterpret_cast<const float4*>(s_bl + d * DSTR + uoff);
            float4 nla = *reinterpret_cast<const float4*>(s_la + d * DSTR + uoff);
            float vleft = __shfl_up_sync(0xffffffffu, v3,    1);
            float lleft = __shfl_up_sync(0xffffffffu, cla.w, 1);
            if (lane == 0) vleft = 0.0f;
            float nv0 = fmaf(v0, cbl.x, vleft * lleft);
            float nv1 = fmaf(v1, cbl.y, v0 * cla.x);
            float nv2 = fmaf(v2, cbl.z, v1 * cla.y);
            float nv3 = fmaf(v3, cbl.w, v2 * cla.z);
            v0 = nv0; v1 = nv1; v2 = nv2; v3 = nv3;
            cbl = nbl; cla = nla;
            if (--cd == 0) {
                cd = RNORM;
                float mx = fmaxf(fmaxf(m0 ? v0 : 0.0f, m1 ? v1 : 0.0f),
                                 fmaxf(m2 ? v2 : 0.0f, m3 ? v3 : 0.0f));
                mx = warp_max(mx);
                int e = (__float_as_int(mx) >> 23) & 0xFF;
                e = max(e, 1);
                float sc = __int_as_float((254 - e) << 23);  // 2^(127-e)
                v0 *= sc; v1 *= sc; v2 *= sc; v3 *= sc;
                K += e - 127;
            }
        }
        {   // final renorm
            float mx = fmaxf(fmaxf(m0 ? v0 : 0.0f, m1 ? v1 : 0.0f),
                             fmaxf(m2 ? v2 : 0.0f, m3 ? v3 : 0.0f));
            mx = warp_max(mx);
            int e = (__float_as_int(mx) >> 23) & 0xFF;
            e = max(e, 1);
            float sc = __int_as_float((254 - e) << 23);
            v0 *= sc; v1 *= sc; v2 *= sc; v3 *= sc;
            K += e - 127;
        }
        *reinterpret_cast<float4*>(s_alp + uoff) = make_float4(v0, v1, v2, v3);
        if (lane == 0) s_ki[0] = K;
    } else {
        // =================== BACKWARD beta': diag dtar-1 .. dm ===============
        float corner = s_bl[dtar * DSTR + ul];   // beta[tl-1][ul] = pb' there
        float w0 = (u0     == ul) ? corner : 0.0f;
        float w1 = (u0 + 1 == ul) ? corner : 0.0f;
        float w2 = (u0 + 2 == ul) ? corner : 0.0f;
        float w3 = (u0 + 3 == ul) ? corner : 0.0f;
        float wr = __shfl_down_sync(0xffffffffu, w0, 1);
        int K = 0, cd = RNORM;
        float4 cbl, cla;
        if (dtar > dm) {
            cbl = *reinterpret_cast<const float4*>(s_bl + (dtar - 1) * DSTR + uoff);
            cla = *reinterpret_cast<const float4*>(s_la + (dtar - 1) * DSTR + uoff);
        }
        for (int d = dtar - 1; d >= dm; --d) {
            int dn = max(d - 1, 0);
            float4 nbl = *reinterpret_cast<const float4*>(s_bl + dn * DSTR + uoff);
            float4 nla = *reinterpret_cast<const float4*>(s_la + dn * DSTR + uoff);
            float nb0 = fmaf(w0, cbl.x, w1 * cla.x);
            float nwr = __shfl_down_sync(0xffffffffu, nb0, 1);
            float nb1 = fmaf(w1, cbl.y, w2 * cla.y);
            float nb2 = fmaf(w2, cbl.z, w3 * cla.z);
            float nb3 = fmaf(w3, cbl.w, wr * cla.w);  // cell 87: cla.w = 0 pad
            w0 = nb0; w1 = nb1; w2 = nb2; w3 = nb3; wr = nwr;
            cbl = nbl; cla = nla;
            if (--cd == 0) {
                cd = RNORM;
                float mx = warp_max(fmaxf(fmaxf(w0, w1), fmaxf(w2, w3)));
                int e = (__float_as_int(mx) >> 23) & 0xFF;
                e = max(e, 1);
                float sc = __int_as_float((254 - e) << 23);
                w0 *= sc; w1 *= sc; w2 *= sc; w3 *= sc;
                wr *= sc;
                K += e - 127;
            }
        }
        {   // final renorm
            float mx = warp_max(fmaxf(fmaxf(w0, w1), fmaxf(w2, w3)));
            int e = (__float_as_int(mx) >> 23) & 0xFF;
            e = max(e, 1);
            float sc = __int_as_float((254 - e) << 23);
            w0 *= sc; w1 *= sc; w2 *= sc; w3 *= sc;
            K += e - 127;
        }
        *reinterpret_cast<float4*>(s_bet + uoff) = make_float4(w0, w1, w2, w3);
        if (lane == 0) s_ki[1] = K;
    }

    asm volatile("bar.sync 1, 64;" ::: "memory");
    if (wid != 0) return;

    // ---------------- Combine at the cut: masked dot product ----------------
    int lo = max(0, dm - (tl - 1));
    int hi = min(dm, ul);
    float S = 0.0f;
    {
        int u = lane;
        if (u >= lo && u <= hi) S += s_alp[u] * s_bet[u];
        u = lane + 32;
        if (u >= lo && u <= hi) S += s_alp[u] * s_bet[u];
        u = lane + 64;
        if (u < 88 && u >= lo && u <= hi) S += s_alp[u] * s_bet[u];
    }
    S = warp_sum(S);

    if (lane == 0) {
        float l;  asm("lg2.approx.f32 %0, %1;" : "=f"(l) : "f"(S));
        g_ll[b] = l - (float)(SC * (dtar + 1)) + (float)(s_ki[0] + s_ki[1]);
        __threadfence();
        int prev = atomicAdd(&g_done, 1);
        if (prev == Bb - 1) {
            __threadfence();
            float sll = 0.0f;
#pragma unroll
            for (int i = 0; i < Bb; ++i) sll += __ldcg(&g_ll[i]);
            out[0] = sll * (-LN2 / (float)Bb);
            g_done = 0;                           // reset for next graph replay
        }
    }
}

extern "C" void kernel_launch(void* const* d_in, const int* in_sizes, int n_in,
                              void* d_out, int out_size) {
    const float* logits  = (const float*)d_in[0];
    const int*   targets = (const int*)d_in[1];
    const int*   tl      = (const int*)d_in[2];
    const int*   ul      = (const int*)d_in[3];

    const int ROWS = Bb * Tt * U1;                 // 207360 rows, 8 warps/block
    lse_kernel<<<PADB + ROWS / 8, 256>>>(logits, targets, tl, ul);

    size_t smem = (2 * NDIAG * DSTR + 256) * sizeof(float);  // tables + buffers
    cudaFuncSetAttribute(dp_kernel, cudaFuncAttributeMaxDynamicSharedMemorySize, (int)smem);

    cudaLaunchConfig_t cfg = {};
    cfg.gridDim  = dim3(Bb);
    cfg.blockDim = dim3(128);
    cfg.dynamicSmemBytes = smem;
    cfg.stream = 0;
    cudaLaunchAttribute attrs[1];
    attrs[0].id = cudaLaunchAttributeProgrammaticStreamSerialization;
    attrs[0].val.programmaticStreamSerializationAllowed = 1;
    cfg.attrs = attrs;
    cfg.numAttrs = 1;
    cudaLaunchKernelEx(&cfg, dp_kernel, tl, ul, (float*)d_out);
}

// round 16
// speedup vs baseline: 1.0758x; 1.0758x over previous
#include <cuda_runtime.h>

#define Bb 16
#define Tt 160
#define Uu 80
#define U1 81
#define Vv 512
#define NDIAG 240     // diagonals d = t+u in [0,239]
#define DSTR 88       // diagonal row stride (floats), 16B aligned
#define L2E 1.4426950408889634f
#define LN2 0.6931471805599453f
#define PADB Bb       // pad-fill blocks prepended to lse grid
#define RNORM 12      // diagonals between renormalizations
#define SC 9          // tables pre-scaled by 2^SC (2^9 = 512)

// Scratch (allocation-free rule). Tables: LINEAR probabilities * 2^SC,
// anti-diagonal layout. Dead rows / geometry pads hold exact 0.0f.
__device__ float g_blank[Bb*NDIAG*DSTR];
__device__ float g_lab  [Bb*NDIAG*DSTR];
__device__ float g_ll   [Bb];
__device__ int   g_done;              // dp completion counter; self-resetting

// ---------------------------------------------------------------------------
__device__ __forceinline__ float exp_fast(float x) {   // deg-4, for numerators
    const float MAGIC = 12582912.0f;                    // 1.5 * 2^23
    float z = fmaf(x, L2E, MAGIC);
    float w = z - MAGIC;
    float f = fmaf(x, L2E, -w);
    float p =               9.6181291076e-3f;
    p = fmaf(p, f, 5.5504108664e-2f);
    p = fmaf(p, f, 2.4022650696e-1f);
    p = fmaf(p, f, 6.9314718056e-1f);
    p = fmaf(p, f, 1.0f);
    return __int_as_float(__float_as_int(p) + (__float_as_int(z) << 23));
}

__device__ __forceinline__ float exp_fast3(float x) {  // deg-3, denominator sum
    const float MAGIC = 12582912.0f;
    float z = fmaf(x, L2E, MAGIC);
    float w = z - MAGIC;
    float f = fmaf(x, L2E, -w);
    float p =               5.5504108664e-2f;
    p = fmaf(p, f, 2.4022650696e-1f);
    p = fmaf(p, f, 6.9314718056e-1f);
    p = fmaf(p, f, 1.0f);
    return __int_as_float(__float_as_int(p) + (__float_as_int(z) << 23));
}

__device__ __forceinline__ void cp16(unsigned int s, const void* g) {
    asm volatile("cp.async.cg.shared.global [%0], [%1], 16;" :: "r"(s), "l"(g));
}

__device__ __forceinline__ float warp_max(float x) {
#pragma unroll
    for (int o = 16; o; o >>= 1) x = fmaxf(x, __shfl_xor_sync(0xffffffffu, x, o));
    return x;
}
__device__ __forceinline__ float warp_sum(float x) {
#pragma unroll
    for (int o = 16; o; o >>= 1) x += __shfl_xor_sync(0xffffffffu, x, o);
    return x;
}

// ---------------------------------------------------------------------------
// Kernel 1: blocks [0,PADB): pad fill (0.0f). Blocks >= PADB: per-row softmax
// denominator; emits LINEAR probs * 2^SC (dead rows write 0 and skip traffic).
// ---------------------------------------------------------------------------
__global__ void __launch_bounds__(256) lse_kernel(const float* __restrict__ logits,
                                                  const int* __restrict__ targets,
                                                  const int* __restrict__ tl_arr,
                                                  const int* __restrict__ ul_arr) {
    cudaTriggerProgrammaticLaunchCompletion();

    if (blockIdx.x < PADB) {
        int b = blockIdx.x;
        float* bbl = g_blank + b * NDIAG * DSTR;
        float* bla = g_lab   + b * NDIAG * DSTR;
        for (int idx = threadIdx.x; idx < NDIAG * DSTR; idx += 256) {
            int d = idx / DSTR;
            int u = idx - d * DSTR;
            int lo = max(0, d - 159), hi = min(d, 80);
            if (u < lo || u > hi) { bbl[idx] = 0.0f; bla[idx] = 0.0f; }
        }
        return;
    }

    int gw   = ((blockIdx.x - PADB) * 256 + threadIdx.x) >> 5;  // row id
    int lane = threadIdx.x & 31;

    int u  = gw % U1;
    int bt = gw / U1;
    int t  = bt % Tt;
    int b  = bt / Tt;
    int o  = (b * NDIAG + (t + u)) * DSTR + u;
    if (t >= __ldg(tl_arr + b) || u > __ldg(ul_arr + b)) {  // dead row -> 0
        if (lane == 0) { g_blank[o] = 0.0f; g_lab[o] = 0.0f; }
        return;
    }

    // Hoist the label gather (dependent 2-load chain) ahead of the stream;
    // all lanes load the same addresses (broadcast) so it's one line each.
    int   tgt       = __ldg(targets + b * Uu + min(u, Uu - 1));
    float lab_logit = __ldg(logits + (size_t)gw * Vv + tgt);

    const float4* p = reinterpret_cast<const float4*>(logits) + (size_t)gw * (Vv / 4);
    float4 a  = __ldcs(p + lane);
    float4 b4 = __ldcs(p + lane + 32);
    float4 c  = __ldcs(p + lane + 64);
    float4 dd = __ldcs(p + lane + 96);

    float s0 = (exp_fast3(a.x)  + exp_fast3(a.y))  + (exp_fast3(a.z)  + exp_fast3(a.w));
    float s1 = (exp_fast3(b4.x) + exp_fast3(b4.y)) + (exp_fast3(b4.z) + exp_fast3(b4.w));
    float s2 = (exp_fast3(c.x)  + exp_fast3(c.y))  + (exp_fast3(c.z)  + exp_fast3(c.w));
    float s3 = (exp_fast3(dd.x) + exp_fast3(dd.y)) + (exp_fast3(dd.z) + exp_fast3(dd.w));
    float s  = (s0 + s1) + (s2 + s3);
#pragma unroll
    for (int o2 = 16; o2; o2 >>= 1) s += __shfl_xor_sync(0xffffffffu, s, o2);

    float blank_logit = __shfl_sync(0xffffffffu, dd.w, 31);  // element 511

    if (lane == 0) {
        float rs = __fdividef(512.0f, s);     // 2^SC / sum  (MUFU rcp path)
        g_blank[o] = exp_fast(blank_logit) * rs;   // pb * 2^SC
        g_lab[o]   = exp_fast(lab_logit)   * rs;   // pl * 2^SC
    }
}

// ---------------------------------------------------------------------------
// Kernel 2: MITM DP in LINEAR domain, one 128-thread block per batch (PDL).
//   warp0: forward alpha to cut dm (1 MUL + 1 FMA per cell per diagonal)
//   warp1: backward beta to dm; warps 2-3 assist cp.async preload then exit.
// Renorm every RNORM diagonals: warp-max -> scale by 2^(127-e), accumulate k.
// Combine: ll = lg2(sum_u A'[u]B'[u]) - SC*(dtar+1) + KF + KB   (log2 domain).
// ---------------------------------------------------------------------------
__global__ void __launch_bounds__(128) dp_kernel(const int* __restrict__ tl_arr,
                                                 const int* __restrict__ ul_arr,
                                                 float* __restrict__ out) {
    extern __shared__ float sm[];
    float* s_bl  = sm;
    float* s_la  = sm + NDIAG * DSTR;
    float* s_alp = sm + 2 * NDIAG * DSTR;        // 88: alpha' at the cut
    float* s_bet = s_alp + 88;                   // 88: beta'  at the cut
    int*   s_ki  = reinterpret_cast<int*>(s_bet + 88);  // [KF, KB]
    int b = blockIdx.x;

    int tl = __ldg(tl_arr + b), ul = __ldg(ul_arr + b);
    int dtar = tl - 1 + ul;
    int dm   = dtar >> 1;
    int n4   = (dtar + 1) * (DSTR / 4);
    const float4* gb = reinterpret_cast<const float4*>(g_blank + b * NDIAG * DSTR);
    const float4* gl = reinterpret_cast<const float4*>(g_lab   + b * NDIAG * DSTR);
    unsigned int sb = (unsigned int)__cvta_generic_to_shared(s_bl);
    unsigned int sl = (unsigned int)__cvta_generic_to_shared(s_la);

    cudaGridDependencySynchronize();             // HW wait on lse grid

    for (int i = threadIdx.x; i < n4; i += 128) {
        cp16(sb + 16u * i, gb + i);
        cp16(sl + 16u * i, gl + i);
    }
    asm volatile("cp.async.commit_group;");
    asm volatile("cp.async.wait_group 0;");
    __syncthreads();

    int wid  = threadIdx.x >> 5;
    if (wid >= 2) return;                        // preload-only warps exit
    int lane = threadIdx.x & 31;
    int u0   = lane * 4;
    int uoff = min(u0, 84);
    bool m0 = (u0     <= ul), m1 = (u0 + 1 <= ul),
         m2 = (u0 + 2 <= ul), m3 = (u0 + 3 <= ul);

    if (wid == 0) {
        // =================== FORWARD alpha': diag 1 .. dm ====================
        float v0 = (lane == 0) ? 1.0f : 0.0f, v1 = 0.0f, v2 = 0.0f, v3 = 0.0f;
        int K = 0, cd = RNORM;
        float4 cbl = *reinterpret_cast<const float4*>(s_bl + uoff);  // row 0
        float4 cla = *reinterpret_cast<const float4*>(s_la + uoff);
        for (int d = 1; d <= dm; ++d) {
            float4 nbl = *reinterpret_cast<const float4*>(s_bl + d * DSTR + uoff);
            float4 nla = *reinterpret_cast<const float4*>(s_la + d * DSTR + uoff);
            float vleft = __shfl_up_sync(0xffffffffu, v3,    1);
            float lleft = __shfl_up_sync(0xffffffffu, cla.w, 1);
            if (lane == 0) vleft = 0.0f;
            float nv0 = fmaf(v0, cbl.x, vleft * lleft);
            float nv1 = fmaf(v1, cbl.y, v0 * cla.x);
            float nv2 = fmaf(v2, cbl.z, v1 * cla.y);
            float nv3 = fmaf(v3, cbl.w, v2 * cla.z);
            v0 = nv0; v1 = nv1; v2 = nv2; v3 = nv3;
            cbl = nbl; cla = nla;
            if (--cd == 0) {
                cd = RNORM;
                float mx = fmaxf(fmaxf(m0 ? v0 : 0.0f, m1 ? v1 : 0.0f),
                                 fmaxf(m2 ? v2 : 0.0f, m3 ? v3 : 0.0f));
                mx = warp_max(mx);
                int e = (__float_as_int(mx) >> 23) & 0xFF;
                e = max(e, 1);
                float sc = __int_as_float((254 - e) << 23);  // 2^(127-e)
                v0 *= sc; v1 *= sc; v2 *= sc; v3 *= sc;
                K += e - 127;
            }
        }
        {   // final renorm
            float mx = fmaxf(fmaxf(m0 ? v0 : 0.0f, m1 ? v1 : 0.0f),
                             fmaxf(m2 ? v2 : 0.0f, m3 ? v3 : 0.0f));
            mx = warp_max(mx);
            int e = (__float_as_int(mx) >> 23) & 0xFF;
            e = max(e, 1);
            float sc = __int_as_float((254 - e) << 23);
            v0 *= sc; v1 *= sc; v2 *= sc; v3 *= sc;
            K += e - 127;
        }
        *reinterpret_cast<float4*>(s_alp + uoff) = make_float4(v0, v1, v2, v3);
        if (lane == 0) s_ki[0] = K;
    } else {
        // =================== BACKWARD beta': diag dtar-1 .. dm ===============
        float corner = s_bl[dtar * DSTR + ul];   // beta[tl-1][ul] = pb' there
        float w0 = (u0     == ul) ? corner : 0.0f;
        float w1 = (u0 + 1 == ul) ? corner : 0.0f;
        float w2 = (u0 + 2 == ul) ? corner : 0.0f;
        float w3 = (u0 + 3 == ul) ? corner : 0.0f;
        float wr = __shfl_down_sync(0xffffffffu, w0, 1);
        int K = 0, cd = RNORM;
        float4 cbl, cla;
        if (dtar > dm) {
            cbl = *reinterpret_cast<const float4*>(s_bl + (dtar - 1) * DSTR + uoff);
            cla = *reinterpret_cast<const float4*>(s_la + (dtar - 1) * DSTR + uoff);
        }
        for (int d = dtar - 1; d >= dm; --d) {
            int dn = max(d - 1, 0);
            float4 nbl = *reinterpret_cast<const float4*>(s_bl + dn * DSTR + uoff);
            float4 nla = *reinterpret_cast<const float4*>(s_la + dn * DSTR + uoff);
            float nb0 = fmaf(w0, cbl.x, w1 * cla.x);
            float nwr = __shfl_down_sync(0xffffffffu, nb0, 1);
            float nb1 = fmaf(w1, cbl.y, w2 * cla.y);
            float nb2 = fmaf(w2, cbl.z, w3 * cla.z);
            float nb3 = fmaf(w3, cbl.w, wr * cla.w);  // cell 87: cla.w = 0 pad
            w0 = nb0; w1 = nb1; w2 = nb2; w3 = nb3; wr = nwr;
            cbl = nbl; cla = nla;
            if (--cd == 0) {
                cd = RNORM;
                float mx = warp_max(fmaxf(fmaxf(w0, w1), fmaxf(w2, w3)));
                int e = (__float_as_int(mx) >> 23) & 0xFF;
                e = max(e, 1);
                float sc = __int_as_float((254 - e) << 23);
                w0 *= sc; w1 *= sc; w2 *= sc; w3 *= sc;
                wr *= sc;
                K += e - 127;
            }
        }
        {   // final renorm
            float mx = warp_max(fmaxf(fmaxf(w0, w1), fmaxf(w2, w3)));
            int e = (__float_as_int(mx) >> 23) & 0xFF;
            e = max(e, 1);
            float sc = __int_as_float((254 - e) << 23);
            w0 *= sc; w1 *= sc; w2 *= sc; w3 *= sc;
            K += e - 127;
        }
        *reinterpret_cast<float4*>(s_bet + uoff) = make_float4(w0, w1, w2, w3);
        if (lane == 0) s_ki[1] = K;
    }

    asm volatile("bar.sync 1, 64;" ::: "memory");
    if (wid != 0) return;

    // ---------------- Combine at the cut: masked dot product ----------------
    int lo = max(0, dm - (tl - 1));
    int hi = min(dm, ul);
    float S = 0.0f;
    {
        int u = lane;
        if (u >= lo && u <= hi) S += s_alp[u] * s_bet[u];
        u = lane + 32;
        if (u >= lo && u <= hi) S += s_alp[u] * s_bet[u];
        u = lane + 64;
        if (u < 88 && u >= lo && u <= hi) S += s_alp[u] * s_bet[u];
    }
    S = warp_sum(S);

    if (lane == 0) {
        float l;  asm("lg2.approx.f32 %0, %1;" : "=f"(l) : "f"(S));
        g_ll[b] = l - (float)(SC * (dtar + 1)) + (float)(s_ki[0] + s_ki[1]);
        __threadfence();
        int prev = atomicAdd(&g_done, 1);
        if (prev == Bb - 1) {
            __threadfence();
            float sll = 0.0f;
#pragma unroll
            for (int i = 0; i < Bb; ++i) sll += __ldcg(&g_ll[i]);
            out[0] = sll * (-LN2 / (float)Bb);
            g_done = 0;                           // reset for next graph replay
        }
    }
}

extern "C" void kernel_launch(void* const* d_in, const int* in_sizes, int n_in,
                              void* d_out, int out_size) {
    const float* logits  = (const float*)d_in[0];
    const int*   targets = (const int*)d_in[1];
    const int*   tl      = (const int*)d_in[2];
    const int*   ul      = (const int*)d_in[3];

    const int ROWS = Bb * Tt * U1;                 // 207360 rows, 8 warps/block
    lse_kernel<<<PADB + ROWS / 8, 256>>>(logits, targets, tl, ul);

    size_t smem = (2 * NDIAG * DSTR + 256) * sizeof(float);  // tables + buffers
    cudaFuncSetAttribute(dp_kernel, cudaFuncAttributeMaxDynamicSharedMemorySize, (int)smem);

    cudaLaunchConfig_t cfg = {};
    cfg.gridDim  = dim3(Bb);
    cfg.blockDim = dim3(128);
    cfg.dynamicSmemBytes = smem;
    cfg.stream = 0;
    cudaLaunchAttribute attrs[1];
    attrs[0].id = cudaLaunchAttributeProgrammaticStreamSerialization;
    attrs[0].val.programmaticStreamSerializationAllowed = 1;
    cfg.attrs = attrs;
    cfg.numAttrs = 1;
    cudaLaunchKernelEx(&cfg, dp_kernel, tl, ul, (float*)d_out);
}

// round 17
// speedup vs baseline: 1.1453x; 1.0647x over previous
#include <cuda_runtime.h>

#define Bb 16
#define Tt 160
#define Uu 80
#define U1 81
#define Vv 512
#define NDIAG 240     // diagonals d = t+u in [0,239]
#define DSTR 88       // diagonal row stride (floats), 16B aligned
#define L2E 1.4426950408889634f
#define LN2 0.6931471805599453f
#define PADB Bb       // pad-fill blocks prepended to lse grid
#define RNORM 12      // diagonals between renormalizations
#define SC 9          // tables pre-scaled by 2^SC (2^9 = 512)

// Scratch (allocation-free rule). Tables: LINEAR probabilities * 2^SC,
// anti-diagonal layout. Dead rows / geometry pads hold exact 0.0f.
__device__ float g_blank[Bb*NDIAG*DSTR];
__device__ float g_lab  [Bb*NDIAG*DSTR];
__device__ float g_ll   [Bb];
__device__ int   g_done;              // dp completion counter; self-resetting

// ---------------------------------------------------------------------------
__device__ __forceinline__ float exp_fast(float x) {   // deg-4, for numerators
    const float MAGIC = 12582912.0f;                    // 1.5 * 2^23
    float z = fmaf(x, L2E, MAGIC);
    float w = z - MAGIC;
    float f = fmaf(x, L2E, -w);
    float p =               9.6181291076e-3f;
    p = fmaf(p, f, 5.5504108664e-2f);
    p = fmaf(p, f, 2.4022650696e-1f);
    p = fmaf(p, f, 6.9314718056e-1f);
    p = fmaf(p, f, 1.0f);
    return __int_as_float(__float_as_int(p) + (__float_as_int(z) << 23));
}

__device__ __forceinline__ float exp_fast2(float x) {  // deg-2, denominator sum
    const float MAGIC = 12582912.0f;
    float z = fmaf(x, L2E, MAGIC);
    float w = z - MAGIC;
    float f = fmaf(x, L2E, -w);
    float p = fmaf(2.4022650696e-1f, f, 6.9314718056e-1f);
    p = fmaf(p, f, 1.0f);
    return __int_as_float(__float_as_int(p) + (__float_as_int(z) << 23));
}

__device__ __forceinline__ void cp16(unsigned int s, const void* g) {
    asm volatile("cp.async.cg.shared.global [%0], [%1], 16;" :: "r"(s), "l"(g));
}

// max over warp of a NON-NEGATIVE float via integer redux (bit patterns are
// order-isomorphic to values when the sign bit is 0).
__device__ __forceinline__ int warp_imax(int x) {
    int r;
    asm("redux.sync.max.s32 %0, %1, 0xffffffff;" : "=r"(r) : "r"(x));
    return r;
}
__device__ __forceinline__ float warp_sum(float x) {
#pragma unroll
    for (int o = 16; o; o >>= 1) x += __shfl_xor_sync(0xffffffffu, x, o);
    return x;
}

// ---------------------------------------------------------------------------
// Kernel 1: blocks [0,PADB): pad fill (0.0f). Blocks >= PADB: per-row softmax
// denominator; emits LINEAR probs * 2^SC (dead rows write 0 and skip traffic).
// ---------------------------------------------------------------------------
__global__ void __launch_bounds__(256) lse_kernel(const float* __restrict__ logits,
                                                  const int* __restrict__ targets,
                                                  const int* __restrict__ tl_arr,
                                                  const int* __restrict__ ul_arr) {
    cudaTriggerProgrammaticLaunchCompletion();

    if (blockIdx.x < PADB) {
        int b = blockIdx.x;
        float* bbl = g_blank + b * NDIAG * DSTR;
        float* bla = g_lab   + b * NDIAG * DSTR;
        for (int idx = threadIdx.x; idx < NDIAG * DSTR; idx += 256) {
            int d = idx / DSTR;
            int u = idx - d * DSTR;
            int lo = max(0, d - 159), hi = min(d, 80);
            if (u < lo || u > hi) { bbl[idx] = 0.0f; bla[idx] = 0.0f; }
        }
        return;
    }

    int gw   = ((blockIdx.x - PADB) * 256 + threadIdx.x) >> 5;  // row id
    int lane = threadIdx.x & 31;

    int u  = gw % U1;
    int bt = gw / U1;
    int t  = bt % Tt;
    int b  = bt / Tt;
    int o  = (b * NDIAG + (t + u)) * DSTR + u;
    if (t >= __ldg(tl_arr + b) || u > __ldg(ul_arr + b)) {  // dead row -> 0
        if (lane == 0) { g_blank[o] = 0.0f; g_lab[o] = 0.0f; }
        return;
    }

    // Hoisted label gather (broadcast loads; off the streaming critical path).
    int   tgt       = __ldg(targets + b * Uu + min(u, Uu - 1));
    float lab_logit = __ldg(logits + (size_t)gw * Vv + tgt);

    const float4* p = reinterpret_cast<const float4*>(logits) + (size_t)gw * (Vv / 4);
    float4 a  = __ldcs(p + lane);
    float4 b4 = __ldcs(p + lane + 32);
    float4 c  = __ldcs(p + lane + 64);
    float4 dd = __ldcs(p + lane + 96);

    float s0 = (exp_fast2(a.x)  + exp_fast2(a.y))  + (exp_fast2(a.z)  + exp_fast2(a.w));
    float s1 = (exp_fast2(b4.x) + exp_fast2(b4.y)) + (exp_fast2(b4.z) + exp_fast2(b4.w));
    float s2 = (exp_fast2(c.x)  + exp_fast2(c.y))  + (exp_fast2(c.z)  + exp_fast2(c.w));
    float s3 = (exp_fast2(dd.x) + exp_fast2(dd.y)) + (exp_fast2(dd.z) + exp_fast2(dd.w));
    float s  = (s0 + s1) + (s2 + s3);
#pragma unroll
    for (int o2 = 16; o2; o2 >>= 1) s += __shfl_xor_sync(0xffffffffu, s, o2);

    float blank_logit = __shfl_sync(0xffffffffu, dd.w, 31);  // element 511

    if (lane == 0) {
        float rs = __fdividef(512.0f, s);     // 2^SC / sum  (MUFU rcp path)
        g_blank[o] = exp_fast(blank_logit) * rs;   // pb * 2^SC
        g_lab[o]   = exp_fast(lab_logit)   * rs;   // pl * 2^SC
    }
}

// ---------------------------------------------------------------------------
// Kernel 2: MITM DP in LINEAR domain, one 128-thread block per batch (PDL).
//   warp0: forward alpha to cut dm (1 MUL + 1 FMA per cell per diagonal)
//   warp1: backward beta to dm; warps 2-3 assist cp.async preload then exit.
// Renorm every RNORM diagonals: REDUX warp-max -> scale 2^(127-e), accum k.
// Combine: ll = lg2(sum_u A'[u]B'[u]) - SC*(dtar+1) + KF + KB   (log2 domain).
// ---------------------------------------------------------------------------
__global__ void __launch_bounds__(128) dp_kernel(const int* __restrict__ tl_arr,
                                                 const int* __restrict__ ul_arr,
                                                 float* __restrict__ out) {
    extern __shared__ float sm[];
    float* s_bl  = sm;
    float* s_la  = sm + NDIAG * DSTR;
    float* s_alp = sm + 2 * NDIAG * DSTR;        // 88: alpha' at the cut
    float* s_bet = s_alp + 88;                   // 88: beta'  at the cut
    int*   s_ki  = reinterpret_cast<int*>(s_bet + 88);  // [KF, KB]
    int b = blockIdx.x;

    int tl = __ldg(tl_arr + b), ul = __ldg(ul_arr + b);
    int dtar = tl - 1 + ul;
    int dm   = dtar >> 1;
    int n4   = (dtar + 1) * (DSTR / 4);
    const float4* gb = reinterpret_cast<const float4*>(g_blank + b * NDIAG * DSTR);
    const float4* gl = reinterpret_cast<const float4*>(g_lab   + b * NDIAG * DSTR);
    unsigned int sb = (unsigned int)__cvta_generic_to_shared(s_bl);
    unsigned int sl = (unsigned int)__cvta_generic_to_shared(s_la);

    cudaGridDependencySynchronize();             // HW wait on lse grid

    for (int i = threadIdx.x; i < n4; i += 128) {
        cp16(sb + 16u * i, gb + i);
        cp16(sl + 16u * i, gl + i);
    }
    asm volatile("cp.async.commit_group;");
    asm volatile("cp.async.wait_group 0;");
    __syncthreads();

    int wid  = threadIdx.x >> 5;
    if (wid >= 2) return;                        // preload-only warps exit
    int lane = threadIdx.x & 31;
    int u0   = lane * 4;
    int uoff = min(u0, 84);
    bool m0 = (u0     <= ul), m1 = (u0 + 1 <= ul),
         m2 = (u0 + 2 <= ul), m3 = (u0 + 3 <= ul);

    if (wid == 0) {
        // =================== FORWARD alpha': diag 1 .. dm ====================
        float v0 = (lane == 0) ? 1.0f : 0.0f, v1 = 0.0f, v2 = 0.0f, v3 = 0.0f;
        int K = 0, cd = RNORM;
        float4 cbl = *reinterpret_cast<const float4*>(s_bl + uoff);  // row 0
        float4 cla = *reinterpret_cast<const float4*>(s_la + uoff);
        for (int d = 1; d <= dm; ++d) {
            float4 nbl = *reinterpret_cast<const float4*>(s_bl + d * DSTR + uoff);
            float4 nla = *reinterpret_cast<const float4*>(s_la + d * DSTR + uoff);
            float vleft = __shfl_up_sync(0xffffffffu, v3,    1);
            float lleft = __shfl_up_sync(0xffffffffu, cla.w, 1);
            if (lane == 0) vleft = 0.0f;
            float nv0 = fmaf(v0, cbl.x, vleft * lleft);
            float nv1 = fmaf(v1, cbl.y, v0 * cla.x);
            float nv2 = fmaf(v2, cbl.z, v1 * cla.y);
            float nv3 = fmaf(v3, cbl.w, v2 * cla.z);
            v0 = nv0; v1 = nv1; v2 = nv2; v3 = nv3;
            cbl = nbl; cla = nla;
            if (--cd == 0) {
                cd = RNORM;
                float mx = fmaxf(fmaxf(m0 ? v0 : 0.0f, m1 ? v1 : 0.0f),
                                 fmaxf(m2 ? v2 : 0.0f, m3 ? v3 : 0.0f));
                int e = (warp_imax(__float_as_int(mx)) >> 23) & 0xFF;
                e = max(e, 1);
                float sc = __int_as_float((254 - e) << 23);  // 2^(127-e)
                v0 *= sc; v1 *= sc; v2 *= sc; v3 *= sc;
                K += e - 127;
            }
        }
        {   // final renorm (bound values before the cross-warp product)
            float mx = fmaxf(fmaxf(m0 ? v0 : 0.0f, m1 ? v1 : 0.0f),
                             fmaxf(m2 ? v2 : 0.0f, m3 ? v3 : 0.0f));
            int e = (warp_imax(__float_as_int(mx)) >> 23) & 0xFF;
            e = max(e, 1);
            float sc = __int_as_float((254 - e) << 23);
            v0 *= sc; v1 *= sc; v2 *= sc; v3 *= sc;
            K += e - 127;
        }
        *reinterpret_cast<float4*>(s_alp + uoff) = make_float4(v0, v1, v2, v3);
        if (lane == 0) s_ki[0] = K;
    } else {
        // =================== BACKWARD beta': diag dtar-1 .. dm ===============
        float corner = s_bl[dtar * DSTR + ul];   // beta[tl-1][ul] = pb' there
        float w0 = (u0     == ul) ? corner : 0.0f;
        float w1 = (u0 + 1 == ul) ? corner : 0.0f;
        float w2 = (u0 + 2 == ul) ? corner : 0.0f;
        float w3 = (u0 + 3 == ul) ? corner : 0.0f;
        float wr = __shfl_down_sync(0xffffffffu, w0, 1);
        int K = 0, cd = RNORM;
        float4 cbl, cla;
        if (dtar > dm) {
            cbl = *reinterpret_cast<const float4*>(s_bl + (dtar - 1) * DSTR + uoff);
            cla = *reinterpret_cast<const float4*>(s_la + (dtar - 1) * DSTR + uoff);
        }
        for (int d = dtar - 1; d >= dm; --d) {
            int dn = max(d - 1, 0);
            float4 nbl = *reinterpret_cast<const float4*>(s_bl + dn * DSTR + uoff);
            float4 nla = *reinterpret_cast<const float4*>(s_la + dn * DSTR + uoff);
            float nb0 = fmaf(w0, cbl.x, w1 * cla.x);
            float nwr = __shfl_down_sync(0xffffffffu, nb0, 1);
            float nb1 = fmaf(w1, cbl.y, w2 * cla.y);
            float nb2 = fmaf(w2, cbl.z, w3 * cla.z);
            float nb3 = fmaf(w3, cbl.w, wr * cla.w);  // cell 87: cla.w = 0 pad
            w0 = nb0; w1 = nb1; w2 = nb2; w3 = nb3; wr = nwr;
            cbl = nbl; cla = nla;
            if (--cd == 0) {
                cd = RNORM;
                float mx = fmaxf(fmaxf(w0, w1), fmaxf(w2, w3));
                int e = (warp_imax(__float_as_int(mx)) >> 23) & 0xFF;
                e = max(e, 1);
                float sc = __int_as_float((254 - e) << 23);
                w0 *= sc; w1 *= sc; w2 *= sc; w3 *= sc;
                wr *= sc;
                K += e - 127;
            }
        }
        {   // final renorm
            float mx = fmaxf(fmaxf(w0, w1), fmaxf(w2, w3));
            int e = (warp_imax(__float_as_int(mx)) >> 23) & 0xFF;
            e = max(e, 1);
            float sc = __int_as_float((254 - e) << 23);
            w0 *= sc; w1 *= sc; w2 *= sc; w3 *= sc;
            K += e - 127;
        }
        *reinterpret_cast<float4*>(s_bet + uoff) = make_float4(w0, w1, w2, w3);
        if (lane == 0) s_ki[1] = K;
    }

    asm volatile("bar.sync 1, 64;" ::: "memory");
    if (wid != 0) return;

    // ---------------- Combine at the cut: masked dot product ----------------
    int lo = max(0, dm - (tl - 1));
    int hi = min(dm, ul);
    float S = 0.0f;
    {
        int u = lane;
        if (u >= lo && u <= hi) S += s_alp[u] * s_bet[u];
        u = lane + 32;
        if (u >= lo && u <= hi) S += s_alp[u] * s_bet[u];
        u = lane + 64;
        if (u < 88 && u >= lo && u <= hi) S += s_alp[u] * s_bet[u];
    }
    S = warp_sum(S);

    if (lane == 0) {
        float l;  asm("lg2.approx.f32 %0, %1;" : "=f"(l) : "f"(S));
        g_ll[b] = l - (float)(SC * (dtar + 1)) + (float)(s_ki[0] + s_ki[1]);
        __threadfence();
        int prev = atomicAdd(&g_done, 1);
        if (prev == Bb - 1) {
            __threadfence();
            float sll = 0.0f;
#pragma unroll
            for (int i = 0; i < Bb; ++i) sll += __ldcg(&g_ll[i]);
            out[0] = sll * (-LN2 / (float)Bb);
            g_done = 0;                           // reset for next graph replay
        }
    }
}

extern "C" void kernel_launch(void* const* d_in, const int* in_sizes, int n_in,
                              void* d_out, int out_size) {
    const float* logits  = (const float*)d_in[0];
    const int*   targets = (const int*)d_in[1];
    const int*   tl      = (const int*)d_in[2];
    const int*   ul      = (const int*)d_in[3];

    const int ROWS = Bb * Tt * U1;                 // 207360 rows, 8 warps/block
    lse_kernel<<<PADB + ROWS / 8, 256>>>(logits, targets, tl, ul);

    size_t smem = (2 * NDIAG * DSTR + 256) * sizeof(float);  // tables + buffers
    cudaFuncSetAttribute(dp_kernel, cudaFuncAttributeMaxDynamicSharedMemorySize, (int)smem);

    cudaLaunchConfig_t cfg = {};
    cfg.gridDim  = dim3(Bb);
    cfg.blockDim = dim3(128);
    cfg.dynamicSmemBytes = smem;
    cfg.stream = 0;
    cudaLaunchAttribute attrs[1];
    attrs[0].id = cudaLaunchAttributeProgrammaticStreamSerialization;
    attrs[0].val.programmaticStreamSerializationAllowed = 1;
    cfg.attrs = attrs;
    cfg.numAttrs = 1;
    cudaLaunchKernelEx(&cfg, dp_kernel, tl, ul, (float*)d_out);
}